// round 11
// baseline (speedup 1.0000x reference)
#include <cuda_runtime.h>
#include <stdint.h>

// 12-bit ripple-borrow subtractor on binary (0/1) float spikes.
// Boolean-exact collapse: diffs = bits of ((a-b) & 0xFFF) MSB-first,
// borrow = (a < b). Output: [B*12] diffs row-major, then [B] borrow.
//
// R10 = R4/R9 (verified best: 92.3us bench / 88.7us ncu / 6.5 TB/s DRAM)
// with an unpredicated full-tile fast path ONLY (body otherwise identical:
// front-batched loads, distinct output registers, batched stores).
// Session findings: ~6.56 TB/s is the mixed 65/35 R/W stream ceiling, hit by
// every flat variant with occ>=40%; traffic (620.7MB) is irreducible.
// Persistent grids, smem staging, RPT>=4, and register-reusing store chains
// all regress.

#define TPB 256
#define ROWS_PER_THREAD 2
#define TILE_ROWS (TPB * ROWS_PER_THREAD)

__device__ __forceinline__ uint32_t pack12(const uint4& w0, const uint4& w1, const uint4& w2) {
    // index 0 = MSB (bit 11) ... index 11 = LSB (bit 0); inputs are 0.0f/1.0f
    uint32_t v = 0;
    v |= (w0.x ? 1u : 0u) << 11;
    v |= (w0.y ? 1u : 0u) << 10;
    v |= (w0.z ? 1u : 0u) << 9;
    v |= (w0.w ? 1u : 0u) << 8;
    v |= (w1.x ? 1u : 0u) << 7;
    v |= (w1.y ? 1u : 0u) << 6;
    v |= (w1.z ? 1u : 0u) << 5;
    v |= (w1.w ? 1u : 0u) << 4;
    v |= (w2.x ? 1u : 0u) << 3;
    v |= (w2.y ? 1u : 0u) << 2;
    v |= (w2.z ? 1u : 0u) << 1;
    v |= (w2.w ? 1u : 0u);
    return v;
}

__device__ __forceinline__ uint32_t bitf(uint32_t d, int bit) {
    return ((d >> bit) & 1u) * 0x3F800000u;  // 1.0f bits or 0
}

template <bool FULL>
__device__ __forceinline__ void sub12_body(
    const uint4* __restrict__ A4,
    const uint4* __restrict__ B4,
    uint4* __restrict__ D4,
    float* __restrict__ Borrow,
    int tileBase, int tid, int batch)
{
    int rows[ROWS_PER_THREAD];
    uint4 a[ROWS_PER_THREAD][3], b[ROWS_PER_THREAD][3];
    bool valid[ROWS_PER_THREAD];

    // Front-batched loads: all 12 LDG.128 issued before any compute.
#pragma unroll
    for (int r = 0; r < ROWS_PER_THREAD; r++) {
        const int i = tileBase + r * TPB + tid;  // block-strided warp pattern
        rows[r] = i;
        valid[r] = FULL ? true : (i < batch);
        if (valid[r]) {
            a[r][0] = __ldcs(&A4[(size_t)i * 3 + 0]);
            a[r][1] = __ldcs(&A4[(size_t)i * 3 + 1]);
            a[r][2] = __ldcs(&A4[(size_t)i * 3 + 2]);
            b[r][0] = __ldcs(&B4[(size_t)i * 3 + 0]);
            b[r][1] = __ldcs(&B4[(size_t)i * 3 + 1]);
            b[r][2] = __ldcs(&B4[(size_t)i * 3 + 2]);
        }
    }

#pragma unroll
    for (int r = 0; r < ROWS_PER_THREAD; r++) {
        if (!valid[r]) continue;
        const int i = rows[r];

        const uint32_t ia = pack12(a[r][0], a[r][1], a[r][2]);
        const uint32_t ib = pack12(b[r][0], b[r][1], b[r][2]);
        const uint32_t d  = (ia - ib) & 0xFFFu;

        uint4 o0, o1, o2;
        o0.x = bitf(d, 11); o0.y = bitf(d, 10); o0.z = bitf(d, 9); o0.w = bitf(d, 8);
        o1.x = bitf(d, 7);  o1.y = bitf(d, 6);  o1.z = bitf(d, 5); o1.w = bitf(d, 4);
        o2.x = bitf(d, 3);  o2.y = bitf(d, 2);  o2.z = bitf(d, 1); o2.w = bitf(d, 0);

        __stcs(&D4[(size_t)i * 3 + 0], o0);
        __stcs(&D4[(size_t)i * 3 + 1], o1);
        __stcs(&D4[(size_t)i * 3 + 2], o2);
        __stcs(&Borrow[i], __uint_as_float((ia < ib) ? 0x3F800000u : 0u));
    }
}

__global__ void __launch_bounds__(TPB) sub12_kernel(
    const uint4* __restrict__ A4,
    const uint4* __restrict__ B4,
    uint4* __restrict__ D4,
    float* __restrict__ Borrow,
    int batch)
{
    const int tileBase = blockIdx.x * TILE_ROWS;
    const int tid = threadIdx.x;

    if (tileBase + TILE_ROWS <= batch) {
        sub12_body<true>(A4, B4, D4, Borrow, tileBase, tid, batch);
    } else {
        sub12_body<false>(A4, B4, D4, Borrow, tileBase, tid, batch);
    }
}

extern "C" void kernel_launch(void* const* d_in, const int* in_sizes, int n_in,
                              void* d_out, int out_size)
{
    const uint4* A4 = (const uint4*)d_in[0];
    const uint4* B4 = (const uint4*)d_in[1];
    const int batch = in_sizes[0] / 12;

    float* out = (float*)d_out;
    uint4* D4 = (uint4*)out;
    float* Borrow = out + (size_t)batch * 12;

    const int blocks = (batch + TILE_ROWS - 1) / TILE_ROWS;
    sub12_kernel<<<blocks, TPB>>>(A4, B4, D4, Borrow, batch);
}